// round 16
// baseline (speedup 1.0000x reference)
#include <cuda_runtime.h>
#include <cuda_fp16.h>
#include <cstdint>

// Problem constants
#define B_   2
#define T_   2048
#define D_   2048
#define NH   16
#define HD   128
#define FR   64
#define KTOT 2048
#define QK_SCALE 0.08838834764831845f   // 1/sqrt(128)

// ---------------------------------------------------------------------------
// Device-global scratch (allocation-free, graph-capture safe)
// ---------------------------------------------------------------------------
__device__ __half g_x_hi[(size_t)B_ * T_ * D_];          // x as fp16
__device__ __half g_oh[(size_t)B_ * T_ * D_];            // attn out (fp16)
__device__ __half g_wa_h[(size_t)3 * D_ * D_];           // w_attn fp16 [2048][6144]
__device__ __half g_wo_h[(size_t)D_ * D_];               // w_out fp16  [2048][2048]
// Q/K/V single fp16 (K,V RoPE applied; Q unscaled), [B,N,T,H]
__device__ __half g_qh[(size_t)B_ * NH * T_ * HD];
__device__ __half g_kh[(size_t)B_ * NH * T_ * HD];
__device__ __half g_vh[(size_t)B_ * NH * T_ * HD];

__device__ __forceinline__ uint32_t smem_u32(const void* p) {
    uint32_t a;
    asm("{ .reg .u64 t; cvta.to.shared.u64 t, %1; cvt.u32.u64 %0, t; }"
        : "=r"(a) : "l"(p));
    return a;
}
__device__ __forceinline__ void ldsm4(uint32_t& r0, uint32_t& r1, uint32_t& r2,
                                      uint32_t& r3, uint32_t addr) {
    asm volatile("ldmatrix.sync.aligned.m8n8.x4.shared.b16 {%0,%1,%2,%3}, [%4];"
                 : "=r"(r0), "=r"(r1), "=r"(r2), "=r"(r3) : "r"(addr));
}
__device__ __forceinline__ void ldsm4t(uint32_t& r0, uint32_t& r1, uint32_t& r2,
                                       uint32_t& r3, uint32_t addr) {
    asm volatile("ldmatrix.sync.aligned.m8n8.x4.trans.shared.b16 {%0,%1,%2,%3}, [%4];"
                 : "=r"(r0), "=r"(r1), "=r"(r2), "=r"(r3) : "r"(addr));
}
// fp32-accumulate fp16 mma (attention)
#define MMA_H(d, a, b0, b1)                                                    \
    asm volatile("mma.sync.aligned.m16n8k16.row.col.f32.f16.f16.f32 "          \
                 "{%0,%1,%2,%3},{%4,%5,%6,%7},{%8,%9},{%0,%1,%2,%3};"          \
                 : "+f"((d)[0]), "+f"((d)[1]), "+f"((d)[2]), "+f"((d)[3])      \
                 : "r"((a)[0]), "r"((a)[1]), "r"((a)[2]), "r"((a)[3]),         \
                   "r"(b0), "r"(b1))
// fp16-accumulate fp16 mma (projections; rate-hypothesis test)
#define MMA16(d, a, b0, b1)                                                    \
    asm volatile("mma.sync.aligned.m16n8k16.row.col.f16.f16.f16.f16 "          \
                 "{%0,%1},{%2,%3,%4,%5},{%6,%7},{%0,%1};"                      \
                 : "+r"((d)[0]), "+r"((d)[1])                                  \
                 : "r"((a)[0]), "r"((a)[1]), "r"((a)[2]), "r"((a)[3]),         \
                   "r"(b0), "r"(b1))

__device__ __forceinline__ void cpa16(uint32_t dst, const void* src) {
    asm volatile("cp.async.cg.shared.global [%0], [%1], 16;"
                 :: "r"(dst), "l"(src));
}
#define CP_COMMIT() asm volatile("cp.async.commit_group;" ::: "memory")
#define CP_WAIT1()  asm volatile("cp.async.wait_group 1;" ::: "memory")

// ---------------------------------------------------------------------------
// Fused fp32->fp16 conversion for x, w_attn, w_out (one launch)
// ---------------------------------------------------------------------------
#define NX4 ((size_t)B_ * T_ * D_ / 4)
#define NA4 ((size_t)3 * D_ * D_ / 4)
#define NO4 ((size_t)D_ * D_ / 4)

__global__ __launch_bounds__(256) void conv_all(const float* __restrict__ x,
                                                const float* __restrict__ wa,
                                                const float* __restrict__ wo)
{
    size_t i = (size_t)blockIdx.x * 256 + threadIdx.x;
    const float* src;
    __half* dst;
    size_t j;
    if (i < NX4)            { src = x;  dst = g_x_hi; j = i; }
    else if (i < NX4 + NA4) { src = wa; dst = g_wa_h; j = i - NX4; }
    else                    { src = wo; dst = g_wo_h; j = i - NX4 - NA4; }
    float4 f = ((const float4*)src)[j];
    ((__half2*)dst)[2 * j]     = __floats2half2_rn(f.x, f.y);
    ((__half2*)dst)[2 * j + 1] = __floats2half2_rn(f.z, f.w);
}

// ---------------------------------------------------------------------------
// 1-term fp16 GEMM, CTA tile 128x64, 4 warps (2m x 2n), warp tile 64x32,
// BK=64, 3-stage cp.async ring. fp16-accumulate MMA chains of 2 (K=32),
// flushed into fp32 master accumulators.
// MODE 0 (QKV): A=g_x_hi, W=g_wa_h (N=6144); epilogue head split + RoPE(k,v).
// MODE 1 (out): A=g_oh,  W=g_wo_h (N=2048); plain fp32 store.
// ---------------------------------------------------------------------------
#define QSTRIDE 72
#define QA_ELE (128 * QSTRIDE)
#define QW_ELE (64 * QSTRIDE)
#define Q_STAGE_ELE (QA_ELE + QW_ELE)
#define Q_SMEM (3 * Q_STAGE_ELE * 2)        // 82944 bytes

template <int MODE>
__global__ __launch_bounds__(128, 2) void gemm1(
    const float* __restrict__ cosT, const float* __restrict__ sinT,
    float* __restrict__ Cout)
{
    extern __shared__ __half smem_h[];
    const int tid = threadIdx.x;
    const int wid = tid >> 5, lane = tid & 31;
    const int warp_m = wid & 1, warp_n = wid >> 1;
    const int m0 = (int)blockIdx.y << 7, n0 = (int)blockIdx.x << 6;
    const uint32_t sb = smem_u32(smem_h);

    const __half* Ag = MODE ? g_oh : g_x_hi;
    const __half* Wg = MODE ? g_wo_h : g_wa_h;
    const int WN = MODE ? D_ : 3 * D_;

    float acc[4][4][4];
#pragma unroll
    for (int i = 0; i < 4; i++)
#pragma unroll
        for (int j = 0; j < 4; j++)
#pragma unroll
            for (int k = 0; k < 4; k++) acc[i][j][k] = 0.f;

    const uint32_t a_lm = ((warp_m * 64 + (lane & 15)) * QSTRIDE + (lane >> 4) * 8) * 2;
    const uint32_t b_lm = (uint32_t)(QA_ELE +
        (lane & 15) * QSTRIDE + ((lane >> 4) << 3) + warp_n * 32) * 2;

    auto LOAD = [&](int stage, int kc) {
        int k0 = kc << 6;
        uint32_t sbs = sb + (uint32_t)stage * Q_STAGE_ELE * 2;
#pragma unroll
        for (int i = 0; i < 8; i++) {
            int c = tid + (i << 7);
            int r = c >> 3, col = (c & 7) << 3;
            cpa16(sbs + (uint32_t)(r * QSTRIDE + col) * 2,
                  Ag + (size_t)(m0 + r) * KTOT + k0 + col);
        }
#pragma unroll
        for (int i = 0; i < 4; i++) {
            int c = tid + (i << 7);
            int r = c >> 3, col = (c & 7) << 3;
            cpa16(sbs + (uint32_t)QA_ELE * 2 + (uint32_t)(r * QSTRIDE + col) * 2,
                  Wg + (size_t)(k0 + r) * WN + n0 + col);
        }
        CP_COMMIT();
    };

    auto COMPUTE = [&](int st) {
        uint32_t stb = sb + (uint32_t)st * Q_STAGE_ELE * 2;
#pragma unroll
        for (int kp = 0; kp < 2; kp++) {             // K pairs: ks = 2kp, 2kp+1
            uint32_t c16[4][4][2];
#pragma unroll
            for (int mt = 0; mt < 4; mt++)
#pragma unroll
                for (int j = 0; j < 4; j++) {
                    c16[mt][j][0] = 0u;
                    c16[mt][j][1] = 0u;
                }
#pragma unroll
            for (int kk = 0; kk < 2; kk++) {
                const int ks = kp * 2 + kk;
                uint32_t ah[4][4], bh[2][4];
#pragma unroll
                for (int mt = 0; mt < 4; mt++)
                    ldsm4(ah[mt][0], ah[mt][1], ah[mt][2], ah[mt][3],
                          stb + a_lm + (mt * 16 * QSTRIDE + ks * 16) * 2);
#pragma unroll
                for (int nn = 0; nn < 2; nn++)
                    ldsm4t(bh[nn][0], bh[nn][1], bh[nn][2], bh[nn][3],
                           stb + b_lm + (ks * 16 * QSTRIDE) * 2 + nn * 32);
#pragma unroll
                for (int mt = 0; mt < 4; mt++)
#pragma unroll
                    for (int nn = 0; nn < 2; nn++) {
                        MMA16(c16[mt][nn * 2],     ah[mt], bh[nn][0], bh[nn][1]);
                        MMA16(c16[mt][nn * 2 + 1], ah[mt], bh[nn][2], bh[nn][3]);
                    }
            }
            // flush fp16 chain into fp32 master accumulators
#pragma unroll
            for (int mt = 0; mt < 4; mt++)
#pragma unroll
                for (int j = 0; j < 4; j++) {
                    float2 lo = __half22float2(*(__half2*)&c16[mt][j][0]);
                    float2 hi = __half22float2(*(__half2*)&c16[mt][j][1]);
                    acc[mt][j][0] += lo.x;
                    acc[mt][j][1] += lo.y;
                    acc[mt][j][2] += hi.x;
                    acc[mt][j][3] += hi.y;
                }
        }
    };

    const int NI = KTOT / 64;            // 32
    LOAD(0, 0);
    LOAD(1, 1);
#pragma unroll 1
    for (int it = 0; it < NI; it++) {
        CP_WAIT1();
        __syncthreads();
        if (it + 2 < NI) LOAD((it + 2) % 3, it + 2);
        else CP_COMMIT();                // keep group count uniform
        COMPUTE(it % 3);
    }

    // ---------------- epilogue ----------------
    const int rb = lane >> 2;
    const int cb = (lane & 3) * 2;
    if (MODE == 0) {
        int sec = n0 >> 11;              // 0=q 1=k 2=v
        int head = (n0 >> 7) & 15;
        __half* dst = (sec == 0) ? g_qh : (sec == 1 ? g_kh : g_vh);
#pragma unroll
        for (int mt = 0; mt < 4; mt++)
#pragma unroll
            for (int hf = 0; hf < 2; hf++) {
                int m = m0 + warp_m * 64 + mt * 16 + hf * 8 + rb;
                int b = m >> 11, t = m & 2047;
                size_t rowbase = ((size_t)(b * NH + head) * T_ + t) * HD;
#pragma unroll
                for (int j = 0; j < 4; j++) {
                    int n = n0 + warp_n * 32 + j * 8 + cb;
                    int hh = n & 127;
                    float v0 = acc[mt][j][hf * 2];
                    float v1 = acc[mt][j][hf * 2 + 1];
                    if (sec) {
                        float cz = cosT[t * FR + (hh >> 1)];
                        float sz = sinT[t * FR + (hh >> 1)];
                        float r0 = v0 * cz - v1 * sz;
                        float r1 = v0 * sz + v1 * cz;
                        v0 = r0; v1 = r1;
                    }
                    *(__half2*)(dst + rowbase + hh) = __floats2half2_rn(v0, v1);
                }
            }
    } else {
#pragma unroll
        for (int mt = 0; mt < 4; mt++)
#pragma unroll
            for (int hf = 0; hf < 2; hf++) {
                int m = m0 + warp_m * 64 + mt * 16 + hf * 8 + rb;
#pragma unroll
                for (int j = 0; j < 4; j++) {
                    int n = n0 + warp_n * 32 + j * 8 + cb;
                    *(float2*)&Cout[(size_t)m * D_ + n] =
                        make_float2(acc[mt][j][hf * 2], acc[mt][j][hf * 2 + 1]);
                }
            }
    }
}

// ---------------------------------------------------------------------------
// fp16 tensor-core causal flash attention, K/V double-buffered (unchanged).
// QK: S = qh . kh (1 MMA, fp32 acc). PV: O = ph . vh (1 MMA, fp32 acc).
// SMEM: Q + 2x(K,V) = 87040 B -> 2 CTAs/SM.
// ---------------------------------------------------------------------------
#define AT_STRIDE 136
#define AT_TILE   (64 * AT_STRIDE)
#define AT_SMEM_BYTES (5 * AT_TILE * 2)

__global__ __launch_bounds__(128, 2) void attn_mma()
{
    extern __shared__ __half sm_at[];
    const int tid = threadIdx.x, wid = tid >> 5, lane = tid & 31;
    const int qt = 31 - (int)blockIdx.x;
    const int qs = qt << 6;
    const int head = blockIdx.y, b = blockIdx.z;
    const size_t hbase = (size_t)(b * NH + head) * T_ * HD;
    const uint32_t sb = smem_u32(sm_at);

    auto kv_load = [&](int jt, int p) {
        const int j0 = jt << 6;
        uint32_t kb = (uint32_t)(1 + 2 * p) * AT_TILE * 2;
        uint32_t vb = (uint32_t)(2 + 2 * p) * AT_TILE * 2;
#pragma unroll
        for (int i = 0; i < 8; i++) {
            int c = tid + i * 128;
            int r = c >> 4, col = (c & 15) << 3;
            size_t g = hbase + (size_t)(j0 + r) * HD + col;
            uint32_t so = (uint32_t)(r * AT_STRIDE + col) * 2;
            cpa16(sb + kb + so, g_kh + g);
            cpa16(sb + vb + so, g_vh + g);
        }
    };

#pragma unroll
    for (int i = 0; i < 8; i++) {
        int c = tid + i * 128;
        int r = c >> 4, col = (c & 15) << 3;
        cpa16(sb + (uint32_t)(r * AT_STRIDE + col) * 2,
              g_qh + hbase + (size_t)(qs + r) * HD + col);
    }
    kv_load(0, 0);
    CP_COMMIT();

    float oacc[16][4];
#pragma unroll
    for (int i = 0; i < 16; i++)
#pragma unroll
        for (int j = 0; j < 4; j++) oacc[i][j] = 0.f;
    float mA = -1e30f, mB = -1e30f, lA = 0.f, lB = 0.f;

    const uint32_t qbase = sb +
        ((wid * 16 + (lane & 15)) * AT_STRIDE + ((lane >> 4) << 3)) * 2;
    const uint32_t k_lm =
        (((lane & 7) + ((lane >> 4) << 3)) * AT_STRIDE + (((lane >> 3) & 1) << 3)) * 2;
    const uint32_t v_lm =
        ((lane & 15) * AT_STRIDE + ((lane >> 4) << 3)) * 2;

#pragma unroll 1
    for (int jt = 0; jt <= qt; jt++) {
        const int p = jt & 1;
        if (jt < qt) kv_load(jt + 1, p ^ 1);
        CP_COMMIT();
        CP_WAIT1();
        __syncthreads();

        const uint32_t kbase = sb + (uint32_t)(1 + 2 * p) * AT_TILE * 2 + k_lm;
        const uint32_t vbase = sb + (uint32_t)(2 + 2 * p) * AT_TILE * 2 + v_lm;

        float sacc[8][4];
#pragma unroll
        for (int i = 0; i < 8; i++)
#pragma unroll
            for (int j = 0; j < 4; j++) sacc[i][j] = 0.f;

#pragma unroll
        for (int ks = 0; ks < 8; ks++) {
            uint32_t qh[4];
            ldsm4(qh[0], qh[1], qh[2], qh[3], qbase + ks * 32);
#pragma unroll
            for (int np = 0; np < 4; np++) {
                uint32_t kh[4];
                ldsm4(kh[0], kh[1], kh[2], kh[3],
                      kbase + (np * 16 * AT_STRIDE) * 2 + ks * 32);
                MMA_H(sacc[2 * np],     qh, kh[0], kh[1]);
                MMA_H(sacc[2 * np + 1], qh, kh[2], kh[3]);
            }
        }

#pragma unroll
        for (int nt = 0; nt < 8; nt++)
#pragma unroll
            for (int j = 0; j < 4; j++) sacc[nt][j] *= QK_SCALE;
        if (jt == qt) {
            int rA = wid * 16 + (lane >> 2);
            int c0 = 2 * (lane & 3);
#pragma unroll
            for (int nt = 0; nt < 8; nt++) {
                int cc = nt * 8 + c0;
                if (cc > rA)         sacc[nt][0] = -1e30f;
                if (cc + 1 > rA)     sacc[nt][1] = -1e30f;
                if (cc > rA + 8)     sacc[nt][2] = -1e30f;
                if (cc + 1 > rA + 8) sacc[nt][3] = -1e30f;
            }
        }

        float tmA = -1e30f, tmB = -1e30f;
#pragma unroll
        for (int nt = 0; nt < 8; nt++) {
            tmA = fmaxf(tmA, fmaxf(sacc[nt][0], sacc[nt][1]));
            tmB = fmaxf(tmB, fmaxf(sacc[nt][2], sacc[nt][3]));
        }
        tmA = fmaxf(tmA, __shfl_xor_sync(0xffffffffu, tmA, 1));
        tmA = fmaxf(tmA, __shfl_xor_sync(0xffffffffu, tmA, 2));
        tmB = fmaxf(tmB, __shfl_xor_sync(0xffffffffu, tmB, 1));
        tmB = fmaxf(tmB, __shfl_xor_sync(0xffffffffu, tmB, 2));
        float mnA = fmaxf(mA, tmA), mnB = fmaxf(mB, tmB);
        float aAl = __expf(mA - mnA), aBl = __expf(mB - mnB);
        mA = mnA; mB = mnB;

        float psA = 0.f, psB = 0.f;
        uint32_t ph[8][2];
#pragma unroll
        for (int nt = 0; nt < 8; nt++) {
            float p0 = __expf(sacc[nt][0] - mA);
            float p1 = __expf(sacc[nt][1] - mA);
            float p2 = __expf(sacc[nt][2] - mB);
            float p3 = __expf(sacc[nt][3] - mB);
            psA += p0 + p1;
            psB += p2 + p3;
            __half2 hA2 = __floats2half2_rn(p0, p1);
            __half2 hB2 = __floats2half2_rn(p2, p3);
            ph[nt][0] = *(uint32_t*)&hA2;
            ph[nt][1] = *(uint32_t*)&hB2;
        }
        lA = lA * aAl + psA;
        lB = lB * aBl + psB;
#pragma unroll
        for (int nt = 0; nt < 16; nt++) {
            oacc[nt][0] *= aAl;
            oacc[nt][1] *= aAl;
            oacc[nt][2] *= aBl;
            oacc[nt][3] *= aBl;
        }

#pragma unroll
        for (int ks = 0; ks < 4; ks++) {
            uint32_t aph[4] = {ph[2 * ks][0], ph[2 * ks][1],
                               ph[2 * ks + 1][0], ph[2 * ks + 1][1]};
#pragma unroll
            for (int np = 0; np < 8; np++) {
                uint32_t vh[4];
                ldsm4t(vh[0], vh[1], vh[2], vh[3],
                       vbase + (ks * 16 * AT_STRIDE) * 2 + np * 32);
                MMA_H(oacc[2 * np],     aph, vh[0], vh[1]);
                MMA_H(oacc[2 * np + 1], aph, vh[2], vh[3]);
            }
        }
        __syncthreads();
    }

    lA += __shfl_xor_sync(0xffffffffu, lA, 1);
    lA += __shfl_xor_sync(0xffffffffu, lA, 2);
    lB += __shfl_xor_sync(0xffffffffu, lB, 1);
    lB += __shfl_xor_sync(0xffffffffu, lB, 2);
    float invA = 1.f / lA, invB = 1.f / lB;

    int rA = qs + wid * 16 + (lane >> 2);
    int c0 = 2 * (lane & 3);
    size_t baseA = ((size_t)(b * T_ + rA)) * D_ + head * HD;
    size_t baseB = baseA + (size_t)8 * D_;
#pragma unroll
    for (int nt = 0; nt < 16; nt++) {
        int cc = nt * 8 + c0;
        *(__half2*)(g_oh + baseA + cc) =
            __floats2half2_rn(oacc[nt][0] * invA, oacc[nt][1] * invA);
        *(__half2*)(g_oh + baseB + cc) =
            __floats2half2_rn(oacc[nt][2] * invB, oacc[nt][3] * invB);
    }
}

// ---------------------------------------------------------------------------
// Launch. Inputs: x, mask, cos, sin, w_attn, w_out. mask is tril -> causal.
// ---------------------------------------------------------------------------
extern "C" void kernel_launch(void* const* d_in, const int* in_sizes, int n_in,
                              void* d_out, int out_size)
{
    const float* x      = (const float*)d_in[0];
    const float* cosT   = (const float*)d_in[2];
    const float* sinT   = (const float*)d_in[3];
    const float* w_attn = (const float*)d_in[4];
    const float* w_out  = (const float*)d_in[5];
    float* out = (float*)d_out;

    cudaFuncSetAttribute(gemm1<0>, cudaFuncAttributeMaxDynamicSharedMemorySize, Q_SMEM);
    cudaFuncSetAttribute(gemm1<1>, cudaFuncAttributeMaxDynamicSharedMemorySize, Q_SMEM);
    cudaFuncSetAttribute(attn_mma, cudaFuncAttributeMaxDynamicSharedMemorySize,
                         AT_SMEM_BYTES);

    // Preprocessing: fp32 -> fp16 for x + both weights in ONE launch
    conv_all<<<(unsigned)((NX4 + NA4 + NO4) / 256), 256>>>(x, w_attn, w_out);

    // QKV projection (fp16-acc MMA chains, fp32 flush every K=32)
    gemm1<0><<<dim3(96, 32), 128, Q_SMEM>>>(cosT, sinT, nullptr);

    // fp16 tensor-core flash attention (fp32-acc, K/V double-buffered)
    attn_mma<<<dim3(32, NH, B_), 128, AT_SMEM_BYTES>>>();

    // Output projection (fp16-acc MMA chains, fp32 flush every K=32)
    gemm1<1><<<dim3(32, 32), 128, Q_SMEM>>>(cosT, sinT, out);
}

// round 17
// speedup vs baseline: 1.1891x; 1.1891x over previous
#include <cuda_runtime.h>
#include <cuda_fp16.h>
#include <cstdint>

// Problem constants
#define B_   2
#define T_   2048
#define D_   2048
#define NH   16
#define HD   128
#define FR   64
#define KTOT 2048
// 1/sqrt(128) * log2(e): softmax computed in base-2 (exp2f = bare MUFU.EX2)
#define QK_SCALE_LOG2E 0.1275174394f

// ---------------------------------------------------------------------------
// Device-global scratch (allocation-free, graph-capture safe)
// ---------------------------------------------------------------------------
__device__ __half g_x_hi[(size_t)B_ * T_ * D_];          // x as fp16
__device__ __half g_oh[(size_t)B_ * T_ * D_];            // attn out (fp16)
__device__ __half g_wa_h[(size_t)3 * D_ * D_];           // w_attn fp16 [2048][6144]
__device__ __half g_wo_h[(size_t)D_ * D_];               // w_out fp16  [2048][2048]
// Q/K/V single fp16 (K,V RoPE applied; Q unscaled), [B,N,T,H]
__device__ __half g_qh[(size_t)B_ * NH * T_ * HD];
__device__ __half g_kh[(size_t)B_ * NH * T_ * HD];
__device__ __half g_vh[(size_t)B_ * NH * T_ * HD];

__device__ __forceinline__ uint32_t smem_u32(const void* p) {
    uint32_t a;
    asm("{ .reg .u64 t; cvta.to.shared.u64 t, %1; cvt.u32.u64 %0, t; }"
        : "=r"(a) : "l"(p));
    return a;
}
__device__ __forceinline__ void ldsm4(uint32_t& r0, uint32_t& r1, uint32_t& r2,
                                      uint32_t& r3, uint32_t addr) {
    asm volatile("ldmatrix.sync.aligned.m8n8.x4.shared.b16 {%0,%1,%2,%3}, [%4];"
                 : "=r"(r0), "=r"(r1), "=r"(r2), "=r"(r3) : "r"(addr));
}
__device__ __forceinline__ void ldsm4t(uint32_t& r0, uint32_t& r1, uint32_t& r2,
                                       uint32_t& r3, uint32_t addr) {
    asm volatile("ldmatrix.sync.aligned.m8n8.x4.trans.shared.b16 {%0,%1,%2,%3}, [%4];"
                 : "=r"(r0), "=r"(r1), "=r"(r2), "=r"(r3) : "r"(addr));
}
#define MMA_H(d, a, b0, b1)                                                    \
    asm volatile("mma.sync.aligned.m16n8k16.row.col.f32.f16.f16.f32 "          \
                 "{%0,%1,%2,%3},{%4,%5,%6,%7},{%8,%9},{%0,%1,%2,%3};"          \
                 : "+f"((d)[0]), "+f"((d)[1]), "+f"((d)[2]), "+f"((d)[3])      \
                 : "r"((a)[0]), "r"((a)[1]), "r"((a)[2]), "r"((a)[3]),         \
                   "r"(b0), "r"(b1))

__device__ __forceinline__ void cpa16(uint32_t dst, const void* src) {
    asm volatile("cp.async.cg.shared.global [%0], [%1], 16;"
                 :: "r"(dst), "l"(src));
}
#define CP_COMMIT() asm volatile("cp.async.commit_group;" ::: "memory")
#define CP_WAIT1()  asm volatile("cp.async.wait_group 1;" ::: "memory")

// ---------------------------------------------------------------------------
// Fused fp32->fp16 conversion for x, w_attn, w_out (one launch)
// ---------------------------------------------------------------------------
#define NX4 ((size_t)B_ * T_ * D_ / 4)
#define NA4 ((size_t)3 * D_ * D_ / 4)
#define NO4 ((size_t)D_ * D_ / 4)

__global__ __launch_bounds__(256) void conv_all(const float* __restrict__ x,
                                                const float* __restrict__ wa,
                                                const float* __restrict__ wo)
{
    size_t i = (size_t)blockIdx.x * 256 + threadIdx.x;
    const float* src;
    __half* dst;
    size_t j;
    if (i < NX4)            { src = x;  dst = g_x_hi; j = i; }
    else if (i < NX4 + NA4) { src = wa; dst = g_wa_h; j = i - NX4; }
    else                    { src = wo; dst = g_wo_h; j = i - NX4 - NA4; }
    float4 f = ((const float4*)src)[j];
    ((__half2*)dst)[2 * j]     = __floats2half2_rn(f.x, f.y);
    ((__half2*)dst)[2 * j + 1] = __floats2half2_rn(f.z, f.w);
}

// ---------------------------------------------------------------------------
// 1-term fp16 GEMM (fp32 accumulate), CTA tile 128x64, 4 warps (2m x 2n),
// warp tile 64x32, BK=64, 3-stage cp.async ring. W K-major [K][N] via
// ldmatrix.trans.
// MODE 0 (QKV): A=g_x_hi, W=g_wa_h (N=6144); epilogue head split + RoPE(k,v).
// MODE 1 (out): A=g_oh,  W=g_wo_h (N=2048); plain fp32 store.
// ---------------------------------------------------------------------------
#define QSTRIDE 72
#define QA_ELE (128 * QSTRIDE)
#define QW_ELE (64 * QSTRIDE)
#define Q_STAGE_ELE (QA_ELE + QW_ELE)
#define Q_SMEM (3 * Q_STAGE_ELE * 2)        // 82944 bytes

template <int MODE>
__global__ __launch_bounds__(128, 2) void gemm1(
    const float* __restrict__ cosT, const float* __restrict__ sinT,
    float* __restrict__ Cout)
{
    extern __shared__ __half smem_h[];
    const int tid = threadIdx.x;
    const int wid = tid >> 5, lane = tid & 31;
    const int warp_m = wid & 1, warp_n = wid >> 1;
    const int m0 = (int)blockIdx.y << 7, n0 = (int)blockIdx.x << 6;
    const uint32_t sb = smem_u32(smem_h);

    const __half* Ag = MODE ? g_oh : g_x_hi;
    const __half* Wg = MODE ? g_wo_h : g_wa_h;
    const int WN = MODE ? D_ : 3 * D_;

    float acc[4][4][4];
#pragma unroll
    for (int i = 0; i < 4; i++)
#pragma unroll
        for (int j = 0; j < 4; j++)
#pragma unroll
            for (int k = 0; k < 4; k++) acc[i][j][k] = 0.f;

    const uint32_t a_lm = ((warp_m * 64 + (lane & 15)) * QSTRIDE + (lane >> 4) * 8) * 2;
    const uint32_t b_lm = (uint32_t)(QA_ELE +
        (lane & 15) * QSTRIDE + ((lane >> 4) << 3) + warp_n * 32) * 2;

    auto LOAD = [&](int stage, int kc) {
        int k0 = kc << 6;
        uint32_t sbs = sb + (uint32_t)stage * Q_STAGE_ELE * 2;
#pragma unroll
        for (int i = 0; i < 8; i++) {
            int c = tid + (i << 7);
            int r = c >> 3, col = (c & 7) << 3;
            cpa16(sbs + (uint32_t)(r * QSTRIDE + col) * 2,
                  Ag + (size_t)(m0 + r) * KTOT + k0 + col);
        }
#pragma unroll
        for (int i = 0; i < 4; i++) {
            int c = tid + (i << 7);
            int r = c >> 3, col = (c & 7) << 3;
            cpa16(sbs + (uint32_t)QA_ELE * 2 + (uint32_t)(r * QSTRIDE + col) * 2,
                  Wg + (size_t)(k0 + r) * WN + n0 + col);
        }
        CP_COMMIT();
    };

    auto COMPUTE = [&](int st) {
        uint32_t stb = sb + (uint32_t)st * Q_STAGE_ELE * 2;
#pragma unroll
        for (int ks = 0; ks < 4; ks++) {
            uint32_t ah[4][4], bh[2][4];
#pragma unroll
            for (int mt = 0; mt < 4; mt++)
                ldsm4(ah[mt][0], ah[mt][1], ah[mt][2], ah[mt][3],
                      stb + a_lm + (mt * 16 * QSTRIDE + ks * 16) * 2);
#pragma unroll
            for (int nn = 0; nn < 2; nn++)
                ldsm4t(bh[nn][0], bh[nn][1], bh[nn][2], bh[nn][3],
                       stb + b_lm + (ks * 16 * QSTRIDE) * 2 + nn * 32);
#pragma unroll
            for (int mt = 0; mt < 4; mt++)
#pragma unroll
                for (int nn = 0; nn < 2; nn++) {
                    MMA_H(acc[mt][nn * 2],     ah[mt], bh[nn][0], bh[nn][1]);
                    MMA_H(acc[mt][nn * 2 + 1], ah[mt], bh[nn][2], bh[nn][3]);
                }
        }
    };

    const int NI = KTOT / 64;            // 32
    LOAD(0, 0);
    LOAD(1, 1);
#pragma unroll 1
    for (int it = 0; it < NI; it++) {
        CP_WAIT1();
        __syncthreads();
        if (it + 2 < NI) LOAD((it + 2) % 3, it + 2);
        else CP_COMMIT();                // keep group count uniform
        COMPUTE(it % 3);
    }

    // ---------------- epilogue ----------------
    const int rb = lane >> 2;
    const int cb = (lane & 3) * 2;
    if (MODE == 0) {
        int sec = n0 >> 11;              // 0=q 1=k 2=v
        int head = (n0 >> 7) & 15;
        __half* dst = (sec == 0) ? g_qh : (sec == 1 ? g_kh : g_vh);
#pragma unroll
        for (int mt = 0; mt < 4; mt++)
#pragma unroll
            for (int hf = 0; hf < 2; hf++) {
                int m = m0 + warp_m * 64 + mt * 16 + hf * 8 + rb;
                int b = m >> 11, t = m & 2047;
                size_t rowbase = ((size_t)(b * NH + head) * T_ + t) * HD;
#pragma unroll
                for (int j = 0; j < 4; j++) {
                    int n = n0 + warp_n * 32 + j * 8 + cb;
                    int hh = n & 127;
                    float v0 = acc[mt][j][hf * 2];
                    float v1 = acc[mt][j][hf * 2 + 1];
                    if (sec) {
                        float cz = cosT[t * FR + (hh >> 1)];
                        float sz = sinT[t * FR + (hh >> 1)];
                        float r0 = v0 * cz - v1 * sz;
                        float r1 = v0 * sz + v1 * cz;
                        v0 = r0; v1 = r1;
                    }
                    *(__half2*)(dst + rowbase + hh) = __floats2half2_rn(v0, v1);
                }
            }
    } else {
#pragma unroll
        for (int mt = 0; mt < 4; mt++)
#pragma unroll
            for (int hf = 0; hf < 2; hf++) {
                int m = m0 + warp_m * 64 + mt * 16 + hf * 8 + rb;
#pragma unroll
                for (int j = 0; j < 4; j++) {
                    int n = n0 + warp_n * 32 + j * 8 + cb;
                    *(float2*)&Cout[(size_t)m * D_ + n] =
                        make_float2(acc[mt][j][hf * 2], acc[mt][j][hf * 2 + 1]);
                }
            }
    }
}

// ---------------------------------------------------------------------------
// fp16 tensor-core causal flash attention, K/V double-buffered.
// QK: S = qh . kh (1 MMA, fp32 acc); scores scaled by 1/sqrt(H)*log2e and
// softmax computed base-2 (exp2f = bare MUFU.EX2, no extra FMUL).
// PV: O = ph . vh (1 MMA, fp32 acc).
// SMEM: Q + 2x(K,V) = 87040 B -> 2 CTAs/SM.
// ---------------------------------------------------------------------------
#define AT_STRIDE 136
#define AT_TILE   (64 * AT_STRIDE)
#define AT_SMEM_BYTES (5 * AT_TILE * 2)

__global__ __launch_bounds__(128, 2) void attn_mma()
{
    extern __shared__ __half sm_at[];
    const int tid = threadIdx.x, wid = tid >> 5, lane = tid & 31;
    const int qt = 31 - (int)blockIdx.x;
    const int qs = qt << 6;
    const int head = blockIdx.y, b = blockIdx.z;
    const size_t hbase = (size_t)(b * NH + head) * T_ * HD;
    const uint32_t sb = smem_u32(sm_at);

    auto kv_load = [&](int jt, int p) {
        const int j0 = jt << 6;
        uint32_t kb = (uint32_t)(1 + 2 * p) * AT_TILE * 2;
        uint32_t vb = (uint32_t)(2 + 2 * p) * AT_TILE * 2;
#pragma unroll
        for (int i = 0; i < 8; i++) {
            int c = tid + i * 128;
            int r = c >> 4, col = (c & 15) << 3;
            size_t g = hbase + (size_t)(j0 + r) * HD + col;
            uint32_t so = (uint32_t)(r * AT_STRIDE + col) * 2;
            cpa16(sb + kb + so, g_kh + g);
            cpa16(sb + vb + so, g_vh + g);
        }
    };

#pragma unroll
    for (int i = 0; i < 8; i++) {
        int c = tid + i * 128;
        int r = c >> 4, col = (c & 15) << 3;
        cpa16(sb + (uint32_t)(r * AT_STRIDE + col) * 2,
              g_qh + hbase + (size_t)(qs + r) * HD + col);
    }
    kv_load(0, 0);
    CP_COMMIT();

    float oacc[16][4];
#pragma unroll
    for (int i = 0; i < 16; i++)
#pragma unroll
        for (int j = 0; j < 4; j++) oacc[i][j] = 0.f;
    float mA = -1e30f, mB = -1e30f, lA = 0.f, lB = 0.f;

    const uint32_t qbase = sb +
        ((wid * 16 + (lane & 15)) * AT_STRIDE + ((lane >> 4) << 3)) * 2;
    const uint32_t k_lm =
        (((lane & 7) + ((lane >> 4) << 3)) * AT_STRIDE + (((lane >> 3) & 1) << 3)) * 2;
    const uint32_t v_lm =
        ((lane & 15) * AT_STRIDE + ((lane >> 4) << 3)) * 2;

#pragma unroll 1
    for (int jt = 0; jt <= qt; jt++) {
        const int p = jt & 1;
        if (jt < qt) kv_load(jt + 1, p ^ 1);
        CP_COMMIT();
        CP_WAIT1();
        __syncthreads();

        const uint32_t kbase = sb + (uint32_t)(1 + 2 * p) * AT_TILE * 2 + k_lm;
        const uint32_t vbase = sb + (uint32_t)(2 + 2 * p) * AT_TILE * 2 + v_lm;

        // ---- S = Q K^T (1-term fp16, fp32 acc) ----
        float sacc[8][4];
#pragma unroll
        for (int i = 0; i < 8; i++)
#pragma unroll
            for (int j = 0; j < 4; j++) sacc[i][j] = 0.f;

#pragma unroll
        for (int ks = 0; ks < 8; ks++) {
            uint32_t qh[4];
            ldsm4(qh[0], qh[1], qh[2], qh[3], qbase + ks * 32);
#pragma unroll
            for (int np = 0; np < 4; np++) {
                uint32_t kh[4];
                ldsm4(kh[0], kh[1], kh[2], kh[3],
                      kbase + (np * 16 * AT_STRIDE) * 2 + ks * 32);
                MMA_H(sacc[2 * np],     qh, kh[0], kh[1]);
                MMA_H(sacc[2 * np + 1], qh, kh[2], kh[3]);
            }
        }

        // ---- scale (base-2 domain) + causal mask ----
#pragma unroll
        for (int nt = 0; nt < 8; nt++)
#pragma unroll
            for (int j = 0; j < 4; j++) sacc[nt][j] *= QK_SCALE_LOG2E;
        if (jt == qt) {
            int rA = wid * 16 + (lane >> 2);
            int c0 = 2 * (lane & 3);
#pragma unroll
            for (int nt = 0; nt < 8; nt++) {
                int cc = nt * 8 + c0;
                if (cc > rA)         sacc[nt][0] = -1e30f;
                if (cc + 1 > rA)     sacc[nt][1] = -1e30f;
                if (cc > rA + 8)     sacc[nt][2] = -1e30f;
                if (cc + 1 > rA + 8) sacc[nt][3] = -1e30f;
            }
        }

        // ---- online softmax (base-2) ----
        float tmA = -1e30f, tmB = -1e30f;
#pragma unroll
        for (int nt = 0; nt < 8; nt++) {
            tmA = fmaxf(tmA, fmaxf(sacc[nt][0], sacc[nt][1]));
            tmB = fmaxf(tmB, fmaxf(sacc[nt][2], sacc[nt][3]));
        }
        tmA = fmaxf(tmA, __shfl_xor_sync(0xffffffffu, tmA, 1));
        tmA = fmaxf(tmA, __shfl_xor_sync(0xffffffffu, tmA, 2));
        tmB = fmaxf(tmB, __shfl_xor_sync(0xffffffffu, tmB, 1));
        tmB = fmaxf(tmB, __shfl_xor_sync(0xffffffffu, tmB, 2));
        float mnA = fmaxf(mA, tmA), mnB = fmaxf(mB, tmB);
        float aAl = exp2f(mA - mnA), aBl = exp2f(mB - mnB);
        mA = mnA; mB = mnB;

        float psA = 0.f, psB = 0.f;
        uint32_t ph[8][2];
#pragma unroll
        for (int nt = 0; nt < 8; nt++) {
            float p0 = exp2f(sacc[nt][0] - mA);
            float p1 = exp2f(sacc[nt][1] - mA);
            float p2 = exp2f(sacc[nt][2] - mB);
            float p3 = exp2f(sacc[nt][3] - mB);
            psA += p0 + p1;
            psB += p2 + p3;
            __half2 hA2 = __floats2half2_rn(p0, p1);
            __half2 hB2 = __floats2half2_rn(p2, p3);
            ph[nt][0] = *(uint32_t*)&hA2;
            ph[nt][1] = *(uint32_t*)&hB2;
        }
        lA = lA * aAl + psA;
        lB = lB * aBl + psB;
#pragma unroll
        for (int nt = 0; nt < 16; nt++) {
            oacc[nt][0] *= aAl;
            oacc[nt][1] *= aAl;
            oacc[nt][2] *= aBl;
            oacc[nt][3] *= aBl;
        }

        // ---- O += P V (1-term fp16), V b-frags via ldmatrix.trans ----
#pragma unroll
        for (int ks = 0; ks < 4; ks++) {
            uint32_t aph[4] = {ph[2 * ks][0], ph[2 * ks][1],
                               ph[2 * ks + 1][0], ph[2 * ks + 1][1]};
#pragma unroll
            for (int np = 0; np < 8; np++) {
                uint32_t vh[4];
                ldsm4t(vh[0], vh[1], vh[2], vh[3],
                       vbase + (ks * 16 * AT_STRIDE) * 2 + np * 32);
                MMA_H(oacc[2 * np],     aph, vh[0], vh[1]);
                MMA_H(oacc[2 * np + 1], aph, vh[2], vh[3]);
            }
        }
        __syncthreads();                 // buf[jt&1] free for tile jt+2's load
    }

    // ---- finalize: normalize, write fp16 to g_oh [B,T,D] ----
    lA += __shfl_xor_sync(0xffffffffu, lA, 1);
    lA += __shfl_xor_sync(0xffffffffu, lA, 2);
    lB += __shfl_xor_sync(0xffffffffu, lB, 1);
    lB += __shfl_xor_sync(0xffffffffu, lB, 2);
    float invA = 1.f / lA, invB = 1.f / lB;

    int rA = qs + wid * 16 + (lane >> 2);
    int c0 = 2 * (lane & 3);
    size_t baseA = ((size_t)(b * T_ + rA)) * D_ + head * HD;
    size_t baseB = baseA + (size_t)8 * D_;
#pragma unroll
    for (int nt = 0; nt < 16; nt++) {
        int cc = nt * 8 + c0;
        *(__half2*)(g_oh + baseA + cc) =
            __floats2half2_rn(oacc[nt][0] * invA, oacc[nt][1] * invA);
        *(__half2*)(g_oh + baseB + cc) =
            __floats2half2_rn(oacc[nt][2] * invB, oacc[nt][3] * invB);
    }
}

// ---------------------------------------------------------------------------
// Launch. Inputs: x, mask, cos, sin, w_attn, w_out. mask is tril -> causal.
// ---------------------------------------------------------------------------
extern "C" void kernel_launch(void* const* d_in, const int* in_sizes, int n_in,
                              void* d_out, int out_size)
{
    const float* x      = (const float*)d_in[0];
    const float* cosT   = (const float*)d_in[2];
    const float* sinT   = (const float*)d_in[3];
    const float* w_attn = (const float*)d_in[4];
    const float* w_out  = (const float*)d_in[5];
    float* out = (float*)d_out;

    cudaFuncSetAttribute(gemm1<0>, cudaFuncAttributeMaxDynamicSharedMemorySize, Q_SMEM);
    cudaFuncSetAttribute(gemm1<1>, cudaFuncAttributeMaxDynamicSharedMemorySize, Q_SMEM);
    cudaFuncSetAttribute(attn_mma, cudaFuncAttributeMaxDynamicSharedMemorySize,
                         AT_SMEM_BYTES);

    // Preprocessing: fp32 -> fp16 for x + both weights in ONE launch
    conv_all<<<(unsigned)((NX4 + NA4 + NO4) / 256), 256>>>(x, w_attn, w_out);

    // QKV projection (fp32-acc 1-term fp16, BK=64)
    gemm1<0><<<dim3(96, 32), 128, Q_SMEM>>>(cosT, sinT, nullptr);

    // fp16 tensor-core flash attention (fp32-acc, K/V double-buffered, exp2)
    attn_mma<<<dim3(32, NH, B_), 128, AT_SMEM_BYTES>>>();

    // Output projection (fp32-acc 1-term fp16)
    gemm1<1><<<dim3(32, 32), 128, Q_SMEM>>>(cosT, sinT, out);
}